// round 16
// baseline (speedup 1.0000x reference)
#include <cuda_runtime.h>
#include <math.h>

// ---------------------------------------------------------------------------
// Problem constants
// ---------------------------------------------------------------------------
#define NB   64
#define TT   800
#define HH   512
#define H2   1024
#define H3   3072   // 3*H2
#define H4   2048   // 4*H
#define OO   80
#define RR   2

#define CH     32
#define NCHUNK (TT / CH)      // 25

typedef unsigned long long ull;

// ---------------------------------------------------------------------------
// Scratch
// ---------------------------------------------------------------------------
#define GSZ (NB * H3)
#define OFF_GI_ATT   0
#define OFF_GH_ATT   (1 * GSZ)
#define OFF_GI_D1    (2 * GSZ)
#define OFF_GH_D1    (3 * GSZ)
#define OFF_GI_D2    (4 * GSZ)
#define OFF_GH_D2    (5 * GSZ)
#define OFF_PRE_A    (6 * GSZ)
#define OFF_PRE      (OFF_PRE_A   + NB * H2)
#define OFF_DP       (OFF_PRE     + NB * HH)
#define OFF_RESID_SC (OFF_DP      + NB * H2)
#define OFF_RESID    (OFF_RESID_SC+ NB * H2)
#define OFF_RESID2   (OFF_RESID   + NB * H2)
#define OFF_DECIN    (OFF_RESID2  + NB * H2)
#define OFF_SSUM     (OFF_DECIN   + NB * H4)
#define OFF_FLAGS    (OFF_SSUM    + 64)     // 48 ints + spare
#define OFF_DUMMY    (OFF_FLAGS   + 60)
#define OFF_HATT     (OFF_FLAGS   + 64)
#define OFF_HD1      (OFF_HATT    + NB * H2)
#define OFF_HD2      (OFF_HD1     + NB * H2)
#define SCRATCH_TOTAL (OFF_HD2    + NB * H2)

__device__ __align__(256) float g_scratch[SCRATCH_TOTAL];

// ---------------------------------------------------------------------------
// PDL primitives (sm_90+)
// ---------------------------------------------------------------------------
__device__ __forceinline__ void gdc_launch() {
    asm volatile("griddepcontrol.launch_dependents;" :::);
}
__device__ __forceinline__ void gdc_wait() {
    asm volatile("griddepcontrol.wait;" ::: "memory");
}

// ---------------------------------------------------------------------------
// Math helpers
// ---------------------------------------------------------------------------
__device__ __forceinline__ float fast_tanh(float x) {
    float e = __expf(2.0f * x);
    return 1.0f - 2.0f / (e + 1.0f);
}
__device__ __forceinline__ float approx_tanh(float x) {
    float y;
    asm("tanh.approx.f32 %0, %1;" : "=f"(y) : "f"(x));
    return y;
}
__device__ __forceinline__ float fast_sigmoid(float x) {
    return 1.0f / (1.0f + __expf(-x));
}
__device__ __forceinline__ ull pk2(float x, float y) {
    ull r;
    asm("mov.b64 %0, {%1, %2};" : "=l"(r) : "f"(x), "f"(y));
    return r;
}
__device__ __forceinline__ void upk2(ull v, float& x, float& y) {
    asm("mov.b64 {%0, %1}, %2;" : "=f"(x), "=f"(y) : "l"(v));
}
__device__ __forceinline__ void ffma2(ull& d, ull a, ull b) {
    asm("fma.rn.f32x2 %0, %1, %2, %0;" : "+l"(d) : "l"(a), "l"(b));
}
__device__ __forceinline__ void red4(float* p, float x, float y, float z, float w) {
    asm volatile("red.global.add.v4.f32 [%0], {%1,%2,%3,%4};"
                 :: "l"(p), "f"(x), "f"(y), "f"(z), "f"(w) : "memory");
}

// ---------------------------------------------------------------------------
// GEMM descriptor: C[64, M] += A'[64, K] * W[M rows, stride wld]^T
// Tile 64x128, 128 threads, 8x8 per-thread micro-tile (row-pair f32x2 accs).
// mode: 0 identity, 1 relu(A), 2 divide cols k<1024 by ssum[row]
// slices: 16 flags; all zero -> A == 0 -> skip
// ---------------------------------------------------------------------------
struct GD {
    const float* A; const float* W; float* C;
    const float* ssum; const int* slices;
    int lda, wld, M, K, KS, inner, mode, nCol, start, nBlocks;
};
struct GemmBatch { GD d[4]; int n; };

static inline GD mk(const float* A, int lda, int mode,
        const float* W, int wld, float* C, int M, int K, int KS, int inner,
        const float* ssum, const int* slices) {
    GD d;
    d.A = A; d.W = W; d.C = C; d.ssum = ssum; d.slices = slices;
    d.lda = lda; d.wld = wld; d.M = M; d.K = K; d.KS = KS; d.inner = inner;
    d.mode = mode;
    d.nCol = (M + 127) >> 7; d.start = 0; d.nBlocks = d.nCol * (K / KS);
    return d;
}

__global__ void __launch_bounds__(128, 4) multi_gemm_kernel(GemmBatch P) {
    __shared__ float As[32 * 64];    // 8 KB
    __shared__ float Ws[32 * 128];   // 16 KB

    int b = blockIdx.x;
    GD d = P.d[0];
#pragma unroll
    for (int i = 1; i < 4; i++)
        if (i < P.n && b >= P.d[i].start) d = P.d[i];
    if (d.slices) {          // side-stream only (event-ordered vs init)
        int s = 0;
#pragma unroll
        for (int i = 0; i < 16; i++) s |= d.slices[i];
        if (s == 0) return;
    }
    int lb = b - d.start;
    int colBlock = lb % d.nCol;
    int kBlock = lb / d.nCol;
    int colBase = colBlock * 128;
    int k0 = kBlock * d.KS;

    int tid = threadIdx.x;
    int ty = tid >> 4;          // 0..7 -> rows ty*8..+7
    int tx = tid & 15;          // 0..15 -> cols {tx*4..+3} and {64+tx*4..+3}
    int arow = tid & 63;
    int half = tid >> 6;
    int wcol = tid;             // 0..127
    int gc = colBase + wcol;
    bool wvalid = (gc < d.M);
    const float4 z4 = make_float4(0.f, 0.f, 0.f, 0.f);

    const float* aptr = d.A + (size_t)arow * d.lda;
    const float* wptr = d.W + (size_t)(wvalid ? gc : 0) * d.wld;

    // ---- W prefetch of first 16 k (weights are inputs: dependency-free) ----
    float4 wq[4];
#pragma unroll
    for (int q = 0; q < 4; q++)
        wq[q] = wvalid ? *(const float4*)(wptr + k0 + q * 4) : z4;

    gdc_launch();
    gdc_wait();    // predecessor results (A operand, ssum, C init) now visible

    float wv = 1.0f;
    if (d.mode == 2) wv = 1.0f / fmaxf(d.ssum[arow], 1e-12f);

    ull acc[4][8];
#pragma unroll
    for (int p = 0; p < 4; p++)
#pragma unroll
        for (int c = 0; c < 8; c++) acc[p][c] = pk2(0.0f, 0.0f);

    int nref = d.KS / d.inner;
    int hk = d.inner >> 1;      // k per A-half (8 or 16)
    int nf4 = hk >> 2;          // A float4/thread (2 or 4)
    int nw4 = d.inner >> 2;     // W float4/thread (4 or 8)

    for (int rf = 0; rf < nref; rf++) {
        int kb = k0 + rf * d.inner;
        // ---- A store (transform applied) ----
#pragma unroll 4
        for (int q = 0; q < nf4; q++) {
            int kl = half * hk + q * 4;
            float4 v = *(const float4*)(aptr + kb + kl);
            if (d.mode == 1) {
                v.x = fmaxf(v.x, 0.f); v.y = fmaxf(v.y, 0.f);
                v.z = fmaxf(v.z, 0.f); v.w = fmaxf(v.w, 0.f);
            } else if (d.mode == 2 && (kb + kl) < H2) {
                v.x *= wv; v.y *= wv; v.z *= wv; v.w *= wv;
            }
            As[(kl + 0) * 64 + arow] = v.x; As[(kl + 1) * 64 + arow] = v.y;
            As[(kl + 2) * 64 + arow] = v.z; As[(kl + 3) * 64 + arow] = v.w;
        }
        // ---- W store ----
#pragma unroll 4
        for (int q = 0; q < nw4; q++) {
            float4 u;
            if (rf == 0 && q < 4) u = wq[q];
            else u = wvalid ? *(const float4*)(wptr + kb + q * 4) : z4;
            int kl = q * 4;
            Ws[(kl + 0) * 128 + wcol] = u.x; Ws[(kl + 1) * 128 + wcol] = u.y;
            Ws[(kl + 2) * 128 + wcol] = u.z; Ws[(kl + 3) * 128 + wcol] = u.w;
        }
        __syncthreads();

        // ---- compute ----
#pragma unroll 4
        for (int kk = 0; kk < d.inner; kk++) {
            const float* ab = &As[kk * 64 + ty * 8];
            ulonglong2 Ap0 = *(const ulonglong2*)(ab);
            ulonglong2 Ap1 = *(const ulonglong2*)(ab + 4);
            float4 w0 = *(const float4*)&Ws[kk * 128 + tx * 4];
            float4 w1 = *(const float4*)&Ws[kk * 128 + 64 + tx * 4];
            ull b0 = pk2(w0.x, w0.x), b1 = pk2(w0.y, w0.y);
            ull b2 = pk2(w0.z, w0.z), b3 = pk2(w0.w, w0.w);
            ull b4 = pk2(w1.x, w1.x), b5 = pk2(w1.y, w1.y);
            ull b6 = pk2(w1.z, w1.z), b7 = pk2(w1.w, w1.w);
            ull ap0 = Ap0.x, ap1 = Ap0.y, ap2 = Ap1.x, ap3 = Ap1.y;
            ffma2(acc[0][0], ap0, b0); ffma2(acc[0][1], ap0, b1);
            ffma2(acc[0][2], ap0, b2); ffma2(acc[0][3], ap0, b3);
            ffma2(acc[0][4], ap0, b4); ffma2(acc[0][5], ap0, b5);
            ffma2(acc[0][6], ap0, b6); ffma2(acc[0][7], ap0, b7);
            ffma2(acc[1][0], ap1, b0); ffma2(acc[1][1], ap1, b1);
            ffma2(acc[1][2], ap1, b2); ffma2(acc[1][3], ap1, b3);
            ffma2(acc[1][4], ap1, b4); ffma2(acc[1][5], ap1, b5);
            ffma2(acc[1][6], ap1, b6); ffma2(acc[1][7], ap1, b7);
            ffma2(acc[2][0], ap2, b0); ffma2(acc[2][1], ap2, b1);
            ffma2(acc[2][2], ap2, b2); ffma2(acc[2][3], ap2, b3);
            ffma2(acc[2][4], ap2, b4); ffma2(acc[2][5], ap2, b5);
            ffma2(acc[2][6], ap2, b6); ffma2(acc[2][7], ap2, b7);
            ffma2(acc[3][0], ap3, b0); ffma2(acc[3][1], ap3, b1);
            ffma2(acc[3][2], ap3, b2); ffma2(acc[3][3], ap3, b3);
            ffma2(acc[3][4], ap3, b4); ffma2(acc[3][5], ap3, b5);
            ffma2(acc[3][6], ap3, b6); ffma2(acc[3][7], ap3, b7);
        }
        __syncthreads();
    }

    // ---- epilogue: two 4-col groups per row ----
    int colA = colBase + tx * 4;
    int colB = colBase + 64 + tx * 4;
    bool vA = (colA < d.M), vB = (colB < d.M);
#pragma unroll
    for (int p = 0; p < 4; p++) {
        int r0 = ty * 8 + 2 * p;
        float l0, h0, l1, h1, l2, h2, l3, h3;
        if (vA) {
            upk2(acc[p][0], l0, h0); upk2(acc[p][1], l1, h1);
            upk2(acc[p][2], l2, h2); upk2(acc[p][3], l3, h3);
            red4(&d.C[(size_t)r0 * d.M + colA], l0, l1, l2, l3);
            red4(&d.C[(size_t)(r0 + 1) * d.M + colA], h0, h1, h2, h3);
        }
        if (vB) {
            upk2(acc[p][4], l0, h0); upk2(acc[p][5], l1, h1);
            upk2(acc[p][6], l2, h2); upk2(acc[p][7], l3, h3);
            red4(&d.C[(size_t)r0 * d.M + colB], l0, l1, l2, l3);
            red4(&d.C[(size_t)(r0 + 1) * d.M + colB], h0, h1, h2, h3);
        }
    }
}

// ---------------------------------------------------------------------------
// Init: scratch work pre-wait; d_out bias write post-wait.
// ---------------------------------------------------------------------------
#define INIT_Z4    (6 * GSZ / 4)
#define INIT_SCR   (INIT_Z4 + NB * H2 + NB * HH + NB * H2 + NB * H2 + NB * H2 + 64)
#define INIT_TOTAL (INIT_SCR + NB * RR * OO)

__global__ void init_kernel(float* __restrict__ out,
                            const float* __restrict__ b_pre1,
                            const float* __restrict__ b_pre2,
                            const float* __restrict__ b_ld,
                            const float* __restrict__ b_sc,
                            const float* __restrict__ b_out,
                            const float* __restrict__ h0,
                            const float* __restrict__ h1,
                            const float* __restrict__ h2) {
    gdc_launch();
    if (blockIdx.x < 48) {
        int buf = blockIdx.x >> 4, s = blockIdx.x & 15;
        const float* hsrc = (buf == 0) ? h0 : ((buf == 1) ? h1 : h2);
        const float* base = hsrc + s * 4096;
        int any = 0;
        for (int i = threadIdx.x; i < 4096; i += 256) any |= (base[i] != 0.0f);
        int r = __syncthreads_or(any);
        if (threadIdx.x == 0)
            ((int*)(g_scratch + OFF_FLAGS))[blockIdx.x] = r;
    }
    int idx0 = blockIdx.x * 256 + threadIdx.x;
    int idx = idx0;
    if (idx < INIT_Z4) {
        ((float4*)g_scratch)[idx] = make_float4(0.f, 0.f, 0.f, 0.f);
    } else {
        idx -= INIT_Z4;
        if (idx < NB * H2) { g_scratch[OFF_PRE_A + idx] = b_pre1[idx & (H2 - 1)]; }
        else {
            idx -= NB * H2;
            if (idx < NB * HH) { g_scratch[OFF_PRE + idx] = b_pre2[idx & (HH - 1)]; }
            else {
                idx -= NB * HH;
                if (idx < NB * H2) { g_scratch[OFF_DP + idx] = b_ld[idx & (H2 - 1)]; }
                else {
                    idx -= NB * H2;
                    if (idx < NB * H2) { g_scratch[OFF_RESID_SC + idx] = b_sc[idx & (H2 - 1)]; }
                    else {
                        idx -= NB * H2;
                        if (idx < NB * H2) {
                            int n = idx >> 10, j = idx & (H2 - 1);
                            g_scratch[OFF_DECIN + (size_t)n * H4 + j] = 0.0f;
                        } else {
                            idx -= NB * H2;
                            if (idx < 64) g_scratch[OFF_SSUM + idx] = 0.0f;
                        }
                    }
                }
            }
        }
    }
    gdc_wait();
    int oidx = idx0 - INIT_SCR;
    if (oidx >= 0 && oidx < NB * RR * OO)
        out[oidx] = b_out[oidx % (RR * OO)];
}

// ---------------------------------------------------------------------------
// GRU combine
// ---------------------------------------------------------------------------
__global__ void gru_combine_kernel(const float* __restrict__ gi,
                                   const float* __restrict__ gh,
                                   const float* __restrict__ bih,
                                   const float* __restrict__ bhh,
                                   const float* __restrict__ hprev,
                                   float* __restrict__ hout,
                                   const float* __restrict__ extra_in,
                                   float* __restrict__ extra_out,
                                   int mode) {
    gdc_launch();
    gdc_wait();
    int idx = blockIdx.x * 256 + threadIdx.x;
    if (idx >= NB * H2) return;
    int n = idx >> 10;
    int j = idx & (H2 - 1);
    const float* gin = gi + (size_t)n * H3;
    const float* ghn = gh + (size_t)n * H3;
    float ir = gin[j]           + bih[j];
    float iz = gin[j + H2]      + bih[j + H2];
    float in_ = gin[j + 2 * H2] + bih[j + 2 * H2];
    float hr = ghn[j]           + bhh[j];
    float hz = ghn[j + H2]      + bhh[j + H2];
    float hn = ghn[j + 2 * H2]  + bhh[j + 2 * H2];
    float r = fast_sigmoid(ir + hr);
    float z = fast_sigmoid(iz + hz);
    float nn = fast_tanh(in_ + r * hn);
    float h = (1.0f - z) * nn + z * hprev[idx];
    hout[idx] = h;
    if (mode == 1) {
        extra_out[(size_t)n * H4 + H2 + j] = h;
    } else if (mode == 2) {
        extra_out[idx] = extra_in[idx] + h;
    }
}

// ---------------------------------------------------------------------------
// Fused attention. PDL: Wattn smem load pre-wait, dp load post-wait.
// ---------------------------------------------------------------------------
__global__ void __launch_bounds__(256) attn_fused_kernel(
    const float* __restrict__ attW, const float* __restrict__ enc,
    const float* __restrict__ dp, const float* __restrict__ Wattn,
    const float* __restrict__ battn, const int* __restrict__ lengths,
    float* __restrict__ dec_in, float* __restrict__ ssum) {
    __shared__ float dps[H2];
    __shared__ float was[H2];
    __shared__ float ss[CH];
    int n = blockIdx.y;
    int t0 = blockIdx.x * CH;
    int len = lengths[n];
    if (t0 >= len) return;
    int kmax = min(CH, len - t0);
    int tid = threadIdx.x;

    for (int i = tid; i < H2; i += 256) was[i] = Wattn[i];
    if (tid < CH) ss[tid] = 0.0f;
    gdc_launch();
    gdc_wait();
    for (int i = tid; i < H2; i += 256) dps[i] = dp[(size_t)n * H2 + i];
    __syncthreads();

    int warp = tid >> 5, lane = tid & 31;
    float bb = battn[0];
#pragma unroll
    for (int rep = 0; rep < CH / 8; rep++) {
        int lt = warp + rep * 8;
        if (lt < kmax) {
            const float4* row = (const float4*)(attW + ((size_t)n * TT + t0 + lt) * H2);
            const float4* d4p = (const float4*)dps;
            const float4* w4p = (const float4*)was;
            float s = 0.0f;
#pragma unroll
            for (int it = 0; it < 8; it++) {
                int i = it * 32 + lane;
                float4 v = row[i];
                float4 dd = d4p[i];
                float4 ww = w4p[i];
                s += approx_tanh(v.x + dd.x) * ww.x
                   + approx_tanh(v.y + dd.y) * ww.y
                   + approx_tanh(v.z + dd.z) * ww.z
                   + approx_tanh(v.w + dd.w) * ww.w;
            }
#pragma unroll
            for (int o = 16; o; o >>= 1) s += __shfl_xor_sync(0xffffffffu, s, o);
            if (lane == 0) ss[lt] = __expf(s + bb);
        }
    }
    __syncthreads();

    if (warp == 0) {
        float v = (lane < CH) ? ss[lane] : 0.0f;
#pragma unroll
        for (int o = 16; o; o >>= 1) v += __shfl_xor_sync(0xffffffffu, v, o);
        if (lane == 0) atomicAdd(&ssum[n], v);
    }

    int h = tid * 4;
    const float* ebase = enc + (size_t)n * TT * H2 + (size_t)t0 * H2 + h;
    float a0 = 0.f, a1 = 0.f, a2 = 0.f, a3 = 0.f;
    float c0 = 0.f, c1 = 0.f, c2 = 0.f, c3 = 0.f;
    int t = 0;
#pragma unroll 4
    for (; t + 2 <= kmax; t += 2) {
        float w0 = ss[t], w1 = ss[t + 1];
        float4 e0 = *(const float4*)(ebase + (size_t)t * H2);
        float4 e1 = *(const float4*)(ebase + (size_t)(t + 1) * H2);
        a0 += w0 * e0.x; a1 += w0 * e0.y; a2 += w0 * e0.z; a3 += w0 * e0.w;
        c0 += w1 * e1.x; c1 += w1 * e1.y; c2 += w1 * e1.z; c3 += w1 * e1.w;
    }
    if (t < kmax) {
        float w0 = ss[t];
        float4 e0 = *(const float4*)(ebase + (size_t)t * H2);
        a0 += w0 * e0.x; a1 += w0 * e0.y; a2 += w0 * e0.z; a3 += w0 * e0.w;
    }
    red4(&dec_in[(size_t)n * H4 + h], a0 + c0, a1 + c1, a2 + c2, a3 + c3);
}

// ---------------------------------------------------------------------------
// L2 prefetch of late-stage weights (one float per 128B line)
// ---------------------------------------------------------------------------
__global__ void prefetch_kernel(const float4* __restrict__ a, int n4a,
                                const float4* __restrict__ b, int n4b,
                                const float4* __restrict__ c, int n4c,
                                const float4* __restrict__ e, int n4e) {
    float s = 0.0f;
    int stride = gridDim.x * blockDim.x * 8;
    int base = (blockIdx.x * blockDim.x + threadIdx.x) * 8;
    for (int i = base; i < n4a; i += stride) s += a[i].x;
    for (int i = base; i < n4b; i += stride) s += b[i].x;
    for (int i = base; i < n4c; i += stride) s += c[i].x;
    for (int i = base; i < n4e; i += stride) s += e[i].x;
    if (s == 1.2345e38f) g_scratch[OFF_DUMMY] = s;   // never fires; defeats DCE
}

// ---------------------------------------------------------------------------
// Host helpers
// ---------------------------------------------------------------------------
static bool s_pdl = true;

template <typename F, typename... Args>
static inline void launch_pdl(F kern, dim3 g, dim3 b, Args... args) {
    if (s_pdl) {
        cudaLaunchConfig_t cfg = {};
        cfg.gridDim = g; cfg.blockDim = b; cfg.stream = 0;
        cudaLaunchAttribute at[1];
        at[0].id = cudaLaunchAttributeProgrammaticStreamSerialization;
        at[0].val.programmaticStreamSerializationAllowed = 1;
        cfg.attrs = at; cfg.numAttrs = 1;
        if (cudaLaunchKernelEx(&cfg, kern, args...) == cudaSuccess) return;
        s_pdl = false;
    }
    kern<<<g, b>>>(args...);
}

static inline int pack_batch(GemmBatch& P, GD* ds, int n) {
    int start = 0;
    for (int i = 0; i < n; i++) {
        ds[i].start = start;
        start += ds[i].nBlocks;
        P.d[i] = ds[i];
    }
    for (int i = n; i < 4; i++) P.d[i] = P.d[n - 1];
    P.n = n;
    return start;
}

static inline void launch_gemms_pdl(GD* ds, int n) {
    GemmBatch P;
    int total = pack_batch(P, ds, n);
    launch_pdl(multi_gemm_kernel, dim3(total), dim3(128), P);
}

static inline void launch_gemms_side(GD* ds, int n, cudaStream_t st) {
    GemmBatch P;
    int total = pack_batch(P, ds, n);
    multi_gemm_kernel<<<total, 128, 0, st>>>(P);
}

extern "C" void kernel_launch(void* const* d_in, const int* in_sizes, int n_in,
                              void* d_out, int out_size) {
    static bool s_init = false;
    static cudaStream_t s_side = 0;
    static cudaEvent_t s_ev0 = 0, s_evgh = 0, s_ev1 = 0, s_ev2 = 0;
    static bool s_ok = false;
    if (!s_init) {
        s_init = true;
        cudaStream_t st;
        cudaEvent_t e0, eg, e1, e2;
        if (cudaStreamCreateWithFlags(&st, cudaStreamNonBlocking) == cudaSuccess &&
            cudaEventCreateWithFlags(&e0, cudaEventDisableTiming) == cudaSuccess &&
            cudaEventCreateWithFlags(&eg, cudaEventDisableTiming) == cudaSuccess &&
            cudaEventCreateWithFlags(&e1, cudaEventDisableTiming) == cudaSuccess &&
            cudaEventCreateWithFlags(&e2, cudaEventDisableTiming) == cudaSuccess) {
            s_side = st; s_ev0 = e0; s_evgh = eg; s_ev1 = e1; s_ev2 = e2;
            s_ok = true;
        }
    }

    const float* input_enc   = (const float*)d_in[0];
    const float* attW_enc    = (const float*)d_in[1];
    const float* input_dec   = (const float*)d_in[2];
    const int*   lengths     = (const int*)  d_in[3];
    const float* hidden_att  = (const float*)d_in[4];
    const float* hidden_dec1 = (const float*)d_in[5];
    const float* hidden_dec2 = (const float*)d_in[6];
    const float* W_pre1 = (const float*)d_in[7];
    const float* b_pre1 = (const float*)d_in[8];
    const float* W_pre2 = (const float*)d_in[9];
    const float* b_pre2 = (const float*)d_in[10];
    const float* Wih_att = (const float*)d_in[11];
    const float* Whh_att = (const float*)d_in[12];
    const float* bih_att = (const float*)d_in[13];
    const float* bhh_att = (const float*)d_in[14];
    const float* W_ld  = (const float*)d_in[15];
    const float* b_ld  = (const float*)d_in[16];
    const float* W_attn = (const float*)d_in[17];
    const float* b_attn = (const float*)d_in[18];
    const float* W_sc  = (const float*)d_in[19];
    const float* b_sc  = (const float*)d_in[20];
    const float* Wih_d1 = (const float*)d_in[21];
    const float* Whh_d1 = (const float*)d_in[22];
    const float* bih_d1 = (const float*)d_in[23];
    const float* bhh_d1 = (const float*)d_in[24];
    const float* Wih_d2 = (const float*)d_in[25];
    const float* Whh_d2 = (const float*)d_in[26];
    const float* bih_d2 = (const float*)d_in[27];
    const float* bhh_d2 = (const float*)d_in[28];
    const float* W_out = (const float*)d_in[29];
    const float* b_out = (const float*)d_in[30];

    float* out = (float*)d_out;

    float* sc = nullptr;
    cudaGetSymbolAddress((void**)&sc, g_scratch);

    float* gi_att = sc + OFF_GI_ATT;
    float* gh_att = sc + OFF_GH_ATT;
    float* gi_d1  = sc + OFF_GI_D1;
    float* gh_d1  = sc + OFF_GH_D1;
    float* gi_d2  = sc + OFF_GI_D2;
    float* gh_d2  = sc + OFF_GH_D2;
    float* pre_a  = sc + OFF_PRE_A;
    float* pre    = sc + OFF_PRE;
    float* dp     = sc + OFF_DP;
    float* resid_sc = sc + OFF_RESID_SC;
    float* resid  = sc + OFF_RESID;
    float* resid2 = sc + OFF_RESID2;
    float* dec_in = sc + OFF_DECIN;
    float* ssum   = sc + OFF_SSUM;
    const int* flags = (const int*)(sc + OFF_FLAGS);

    bool full_out = (out_size >= NB * RR * OO + 3 * NB * H2);
    float* h_att_out = full_out ? out + NB * RR * OO : sc + OFF_HATT;
    float* h_d1_out  = full_out ? h_att_out + NB * H2 : sc + OFF_HD1;
    float* h_d2_out  = full_out ? h_d1_out + NB * H2 : sc + OFF_HD2;

    cudaStream_t side = s_ok ? s_side : (cudaStream_t)0;

    // 1) init: flags + zeroing + bias broadcasts (out biases post-wait)
    launch_pdl(init_kernel, dim3((INIT_TOTAL + 255) / 256), dim3(256),
               out, b_pre1, b_pre2, b_ld, b_sc, b_out,
               hidden_att, hidden_dec1, hidden_dec2);

    // fork 1: gh GEMMs on side stream (mostly flag-skipped; off critical path)
    if (s_ok) {
        cudaEventRecord(s_ev0, 0);
        cudaStreamWaitEvent(side, s_ev0, 0);
    }
    {
        GD ds[3] = {
            mk(hidden_att,  H2, 0, Whh_att, H2, gh_att, H3, H2, 128, 32, 0, flags + 0),
            mk(hidden_dec1, H2, 0, Whh_d1,  H2, gh_d1,  H3, H2, 128, 32, 0, flags + 16),
            mk(hidden_dec2, H2, 0, Whh_d2,  H2, gh_d2,  H3, H2, 128, 32, 0, flags + 32),
        };
        launch_gemms_side(ds, 3, side);
    }
    if (s_ok) cudaEventRecord(s_evgh, side);

    // 2) pre_a = input_dec @ W_pre1^T + b1   (40 blocks)
    {
        GD ds[1] = { mk(input_dec, OO, 0, W_pre1, OO, pre_a, H2, OO, 16, 16, 0, 0) };
        launch_gemms_pdl(ds, 1);
    }
    // 3) pre = relu(pre_a) @ W_pre2^T + b2   (256 blocks)
    {
        GD ds[1] = { mk(pre_a, H2, 1, W_pre2, H2, pre, HH, H2, 16, 16, 0, 0) };
        launch_gemms_pdl(ds, 1);
    }
    // 4) gi_att = relu(pre) @ Wih_att^T   (768 blocks)
    {
        GD ds[1] = { mk(pre, HH, 1, Wih_att, HH, gi_att, H3, HH, 16, 16, 0, 0) };
        launch_gemms_pdl(ds, 1);
    }
    // join gh before combine
    if (s_ok) cudaStreamWaitEvent(0, s_evgh, 0);
    // 5) h_att (also writes dec_in h-half)
    launch_pdl(gru_combine_kernel, dim3((NB * H2 + 255) / 256), dim3(256),
               (const float*)gi_att, (const float*)gh_att, bih_att, bhh_att,
               hidden_att, h_att_out, (const float*)0, dec_in, 1);

    // fork 2: side stream computes h_att-half GEMMs + prefetch under attention
    if (s_ok) {
        cudaEventRecord(s_ev1, 0);
        cudaStreamWaitEvent(side, s_ev1, 0);
    }
    {
        GD ds[2] = {
            mk(h_att_out, H2, 0, Wih_d1 + H2, H4, gi_d1,    H3, H2, 64, 32, 0, 0),
            mk(h_att_out, H2, 0, W_sc   + H2, H4, resid_sc, H2, H2, 64, 32, 0, 0),
        };
        launch_gemms_side(ds, 2, side);   // 512 blocks on side stream
    }
    prefetch_kernel<<<64, 256, 0, side>>>(
        (const float4*)Wih_d2, (H3 * H2) / 4,
        (const float4*)W_out, (RR * OO * H2) / 4,
        (const float4*)Wih_d1, (H3 * H4) / 4,
        (const float4*)W_sc, (H2 * H4) / 4);
    if (s_ok) cudaEventRecord(s_ev2, side);

    // 6) dec_proj   (512 blocks)
    {
        GD ds[1] = { mk(h_att_out, H2, 0, W_ld, H2, dp, H2, H2, 16, 16, 0, 0) };
        launch_gemms_pdl(ds, 1);
    }
    // 7) fused attention (1600 blocks) — side-stream GEMMs overlap here
    launch_pdl(attn_fused_kernel, dim3(NCHUNK, NB), dim3(256),
               attW_enc, input_enc, (const float*)dp, W_attn, b_attn,
               lengths, dec_in, ssum);
    // 8) attn-half GEMMs: K=1024, normalize on load (1024 blocks)
    {
        GD ds[2] = {
            mk(dec_in, H4, 2, Wih_d1, H4, gi_d1,    H3, H2, 32, 32, ssum, 0),
            mk(dec_in, H4, 2, W_sc,   H4, resid_sc, H2, H2, 32, 32, ssum, 0),
        };
        launch_gemms_pdl(ds, 2);
    }
    // join side stream before consuming gi_d1 / resid_sc
    if (s_ok) cudaStreamWaitEvent(0, s_ev2, 0);

    // 9) h_dec1 + residual
    launch_pdl(gru_combine_kernel, dim3((NB * H2 + 255) / 256), dim3(256),
               (const float*)gi_d1, (const float*)gh_d1, bih_d1, bhh_d1,
               hidden_dec1, h_d1_out, (const float*)resid_sc, resid, 2);
    // 10) gi_d2   (768 blocks)
    {
        GD ds[1] = { mk(resid, H2, 0, Wih_d2, H2, gi_d2, H3, H2, 32, 32, 0, 0) };
        launch_gemms_pdl(ds, 1);
    }
    // 11) h_dec2 + residual2
    launch_pdl(gru_combine_kernel, dim3((NB * H2 + 255) / 256), dim3(256),
               (const float*)gi_d2, (const float*)gh_d2, bih_d2, bhh_d2,
               hidden_dec2, h_d2_out, (const float*)resid, resid2, 2);
    // 12) output projection   (128 blocks)
    {
        GD ds[1] = { mk(resid2, H2, 0, W_out, H2, out, RR * OO, H2, 16, 16, 0, 0) };
        launch_gemms_pdl(ds, 1);
    }
}

// round 17
// speedup vs baseline: 1.1373x; 1.1373x over previous
#include <cuda_runtime.h>
#include <math.h>

// ---------------------------------------------------------------------------
// Problem constants
// ---------------------------------------------------------------------------
#define NB   64
#define TT   800
#define HH   512
#define H2   1024
#define H3   3072   // 3*H2
#define H4   2048   // 4*H
#define OO   80
#define RR   2

#define CH     32
#define NCHUNK (TT / CH)      // 25

typedef unsigned long long ull;

// ---------------------------------------------------------------------------
// Scratch
// ---------------------------------------------------------------------------
#define GSZ (NB * H3)
#define OFF_GI_ATT   0
#define OFF_GH_ATT   (1 * GSZ)
#define OFF_GI_D1    (2 * GSZ)
#define OFF_GH_D1    (3 * GSZ)
#define OFF_GI_D2    (4 * GSZ)
#define OFF_GH_D2    (5 * GSZ)
#define OFF_PRE_A    (6 * GSZ)
#define OFF_PRE      (OFF_PRE_A   + NB * H2)
#define OFF_DP       (OFF_PRE     + NB * HH)
#define OFF_RESID_SC (OFF_DP      + NB * H2)
#define OFF_RESID    (OFF_RESID_SC+ NB * H2)
#define OFF_RESID2   (OFF_RESID   + NB * H2)
#define OFF_DECIN    (OFF_RESID2  + NB * H2)
#define OFF_SSUM     (OFF_DECIN   + NB * H4)
#define OFF_FLAGS    (OFF_SSUM    + 64)     // 48 ints + spare
#define OFF_DUMMY    (OFF_FLAGS   + 60)
#define OFF_HATT     (OFF_FLAGS   + 64)
#define OFF_HD1      (OFF_HATT    + NB * H2)
#define OFF_HD2      (OFF_HD1     + NB * H2)
#define SCRATCH_TOTAL (OFF_HD2    + NB * H2)

__device__ __align__(256) float g_scratch[SCRATCH_TOTAL];

// ---------------------------------------------------------------------------
// PDL primitives (sm_90+)
// ---------------------------------------------------------------------------
__device__ __forceinline__ void gdc_launch() {
    asm volatile("griddepcontrol.launch_dependents;" :::);
}
__device__ __forceinline__ void gdc_wait() {
    asm volatile("griddepcontrol.wait;" ::: "memory");
}

// ---------------------------------------------------------------------------
// Math helpers
// ---------------------------------------------------------------------------
__device__ __forceinline__ float fast_tanh(float x) {
    float e = __expf(2.0f * x);
    return 1.0f - 2.0f / (e + 1.0f);
}
__device__ __forceinline__ float approx_tanh(float x) {
    float y;
    asm("tanh.approx.f32 %0, %1;" : "=f"(y) : "f"(x));
    return y;
}
__device__ __forceinline__ float fast_sigmoid(float x) {
    return 1.0f / (1.0f + __expf(-x));
}
__device__ __forceinline__ ull pk2(float x, float y) {
    ull r;
    asm("mov.b64 %0, {%1, %2};" : "=l"(r) : "f"(x), "f"(y));
    return r;
}
__device__ __forceinline__ void upk2(ull v, float& x, float& y) {
    asm("mov.b64 {%0, %1}, %2;" : "=f"(x), "=f"(y) : "l"(v));
}
__device__ __forceinline__ void ffma2(ull& d, ull a, ull b) {
    asm("fma.rn.f32x2 %0, %1, %2, %0;" : "+l"(d) : "l"(a), "l"(b));
}
__device__ __forceinline__ void red4(float* p, float x, float y, float z, float w) {
    asm volatile("red.global.add.v4.f32 [%0], {%1,%2,%3,%4};"
                 :: "l"(p), "f"(x), "f"(y), "f"(z), "f"(w) : "memory");
}

// ---------------------------------------------------------------------------
// GEMM descriptor: C[64, M] += A'[64, K] * W[M rows, stride wld]^T
// Tile 64x64, 128 threads, 8x4 per-thread micro-tile (row-pair f32x2 accs).
// mode: 0 identity, 1 relu(A), 2 divide cols k<1024 by ssum[row]
// slices: 16 flags; all zero -> A == 0 -> skip
// ---------------------------------------------------------------------------
struct GD {
    const float* A; const float* W; float* C;
    const float* ssum; const int* slices;
    int lda, wld, M, K, KS, inner, mode, nCol, start, nBlocks;
};
struct GemmBatch { GD d[4]; int n; };

static inline GD mk(const float* A, int lda, int mode,
        const float* W, int wld, float* C, int M, int K, int KS, int inner,
        const float* ssum, const int* slices) {
    GD d;
    d.A = A; d.W = W; d.C = C; d.ssum = ssum; d.slices = slices;
    d.lda = lda; d.wld = wld; d.M = M; d.K = K; d.KS = KS; d.inner = inner;
    d.mode = mode;
    d.nCol = (M + 63) >> 6; d.start = 0; d.nBlocks = d.nCol * (K / KS);
    return d;
}

// One 64x64 tile, 128 threads, two-level split-K with register prefetch,
// red.v4 epilogue. PDL: W prefetch issues BEFORE griddepcontrol.wait.
__global__ void __launch_bounds__(128, 4) multi_gemm_kernel(GemmBatch P) {
    __shared__ float As[2048];
    __shared__ float Ws[2048];

    int b = blockIdx.x;
    GD d = P.d[0];
#pragma unroll
    for (int i = 1; i < 4; i++)
        if (i < P.n && b >= P.d[i].start) d = P.d[i];
    if (d.slices) {
        int s = 0;
#pragma unroll
        for (int i = 0; i < 16; i++) s |= d.slices[i];
        if (s == 0) return;
    }
    int lb = b - d.start;
    int colBlock = lb % d.nCol;
    int kBlock = lb / d.nCol;
    int colBase = colBlock * 64;
    int k0 = kBlock * d.KS;

    int tid = threadIdx.x;
    int ty = tid >> 4;
    int tx = tid & 15;
    int arow = tid & 63;
    int half = tid >> 6;
    int wcol = tid & 63;
    int gc = colBase + wcol;
    bool wvalid = (gc < d.M);
    const float4 z4 = make_float4(0.f, 0.f, 0.f, 0.f);

    const float* aptr = d.A + (size_t)arow * d.lda;
    const float* wptr = d.W + (size_t)(wvalid ? gc : 0) * d.wld;

    int nref = d.KS / d.inner;
    int hk = d.inner >> 1;
    int nf4 = hk >> 2;

    // ---- W prefetch (weights are kernel inputs: dependency-free) ----
    float4 aq[4], wq[4];
#pragma unroll
    for (int q = 0; q < 4; q++) {
        if (q < nf4) {
            int kl = half * hk + q * 4;
            wq[q] = wvalid ? *(const float4*)(wptr + k0 + kl) : z4;
        }
    }
    gdc_launch();
    gdc_wait();    // predecessor results (A operand, ssum, C init) now visible

    float wv = 1.0f;
    if (d.mode == 2) wv = 1.0f / fmaxf(d.ssum[arow], 1e-12f);

#pragma unroll
    for (int q = 0; q < 4; q++) {
        if (q < nf4) {
            int kl = half * hk + q * 4;
            aq[q] = *(const float4*)(aptr + k0 + kl);
        }
    }

    ull acc[4][4];
#pragma unroll
    for (int p = 0; p < 4; p++)
#pragma unroll
        for (int j = 0; j < 4; j++) acc[p][j] = pk2(0.0f, 0.0f);

    int kb = k0;
    for (int rf = 0; rf < nref; rf++) {
#pragma unroll
        for (int q = 0; q < 4; q++) {
            if (q < nf4) {
                int kl = half * hk + q * 4;
                float4 v = aq[q];
                if (d.mode == 1) {
                    v.x = fmaxf(v.x, 0.f); v.y = fmaxf(v.y, 0.f);
                    v.z = fmaxf(v.z, 0.f); v.w = fmaxf(v.w, 0.f);
                } else if (d.mode == 2 && (kb + kl) < H2) {
                    v.x *= wv; v.y *= wv; v.z *= wv; v.w *= wv;
                }
                As[(kl + 0) * 64 + arow] = v.x; As[(kl + 1) * 64 + arow] = v.y;
                As[(kl + 2) * 64 + arow] = v.z; As[(kl + 3) * 64 + arow] = v.w;
                float4 u = wq[q];
                Ws[(kl + 0) * 64 + wcol] = u.x; Ws[(kl + 1) * 64 + wcol] = u.y;
                Ws[(kl + 2) * 64 + wcol] = u.z; Ws[(kl + 3) * 64 + wcol] = u.w;
            }
        }
        __syncthreads();

        if (rf + 1 < nref) {
            int kn = kb + d.inner;
#pragma unroll
            for (int q = 0; q < 4; q++) {
                if (q < nf4) {
                    int kl = half * hk + q * 4;
                    aq[q] = *(const float4*)(aptr + kn + kl);
                    wq[q] = wvalid ? *(const float4*)(wptr + kn + kl) : z4;
                }
            }
        }

#pragma unroll 4
        for (int kk = 0; kk < d.inner; kk++) {
            const float* ab = &As[kk * 64 + ty * 8];
            ulonglong2 Ap0 = *(const ulonglong2*)(ab);
            ulonglong2 Ap1 = *(const ulonglong2*)(ab + 4);
            float4 bv = *(const float4*)&Ws[kk * 64 + tx * 4];
            ull b0 = pk2(bv.x, bv.x);
            ull b1 = pk2(bv.y, bv.y);
            ull b2 = pk2(bv.z, bv.z);
            ull b3 = pk2(bv.w, bv.w);
            ffma2(acc[0][0], Ap0.x, b0); ffma2(acc[0][1], Ap0.x, b1);
            ffma2(acc[0][2], Ap0.x, b2); ffma2(acc[0][3], Ap0.x, b3);
            ffma2(acc[1][0], Ap0.y, b0); ffma2(acc[1][1], Ap0.y, b1);
            ffma2(acc[1][2], Ap0.y, b2); ffma2(acc[1][3], Ap0.y, b3);
            ffma2(acc[2][0], Ap1.x, b0); ffma2(acc[2][1], Ap1.x, b1);
            ffma2(acc[2][2], Ap1.x, b2); ffma2(acc[2][3], Ap1.x, b3);
            ffma2(acc[3][0], Ap1.y, b0); ffma2(acc[3][1], Ap1.y, b1);
            ffma2(acc[3][2], Ap1.y, b2); ffma2(acc[3][3], Ap1.y, b3);
        }
        __syncthreads();
        kb += d.inner;
    }

    int col = colBase + tx * 4;
    if (col < d.M) {
#pragma unroll
        for (int p = 0; p < 4; p++) {
            int r0 = ty * 8 + 2 * p;
            float lo0, hi0, lo1, hi1, lo2, hi2, lo3, hi3;
            upk2(acc[p][0], lo0, hi0);
            upk2(acc[p][1], lo1, hi1);
            upk2(acc[p][2], lo2, hi2);
            upk2(acc[p][3], lo3, hi3);
            red4(&d.C[(size_t)r0 * d.M + col], lo0, lo1, lo2, lo3);
            red4(&d.C[(size_t)(r0 + 1) * d.M + col], hi0, hi1, hi2, hi3);
        }
    }
}

// ---------------------------------------------------------------------------
// Init: scratch work pre-wait; d_out bias write post-wait (races prior
// replay's W_out otherwise). Flags + float4 zero + biases.
// ---------------------------------------------------------------------------
#define INIT_Z4    (6 * GSZ / 4)
#define INIT_SCR   (INIT_Z4 + NB * H2 + NB * HH + NB * H2 + NB * H2 + NB * H2 + 64)
#define INIT_TOTAL (INIT_SCR + NB * RR * OO)

__global__ void init_kernel(float* __restrict__ out,
                            const float* __restrict__ b_pre1,
                            const float* __restrict__ b_pre2,
                            const float* __restrict__ b_ld,
                            const float* __restrict__ b_sc,
                            const float* __restrict__ b_out,
                            const float* __restrict__ h0,
                            const float* __restrict__ h1,
                            const float* __restrict__ h2) {
    gdc_launch();
    if (blockIdx.x < 48) {
        int buf = blockIdx.x >> 4, s = blockIdx.x & 15;
        const float* hsrc = (buf == 0) ? h0 : ((buf == 1) ? h1 : h2);
        const float* base = hsrc + s * 4096;
        int any = 0;
        for (int i = threadIdx.x; i < 4096; i += 256) any |= (base[i] != 0.0f);
        int r = __syncthreads_or(any);
        if (threadIdx.x == 0)
            ((int*)(g_scratch + OFF_FLAGS))[blockIdx.x] = r;
    }
    int idx0 = blockIdx.x * 256 + threadIdx.x;
    int idx = idx0;
    if (idx < INIT_Z4) {
        ((float4*)g_scratch)[idx] = make_float4(0.f, 0.f, 0.f, 0.f);
    } else {
        idx -= INIT_Z4;
        if (idx < NB * H2) { g_scratch[OFF_PRE_A + idx] = b_pre1[idx & (H2 - 1)]; }
        else {
            idx -= NB * H2;
            if (idx < NB * HH) { g_scratch[OFF_PRE + idx] = b_pre2[idx & (HH - 1)]; }
            else {
                idx -= NB * HH;
                if (idx < NB * H2) { g_scratch[OFF_DP + idx] = b_ld[idx & (H2 - 1)]; }
                else {
                    idx -= NB * H2;
                    if (idx < NB * H2) { g_scratch[OFF_RESID_SC + idx] = b_sc[idx & (H2 - 1)]; }
                    else {
                        idx -= NB * H2;
                        if (idx < NB * H2) {
                            int n = idx >> 10, j = idx & (H2 - 1);
                            g_scratch[OFF_DECIN + (size_t)n * H4 + j] = 0.0f;
                        } else {
                            idx -= NB * H2;
                            if (idx < 64) g_scratch[OFF_SSUM + idx] = 0.0f;
                        }
                    }
                }
            }
        }
    }
    gdc_wait();
    int oidx = idx0 - INIT_SCR;
    if (oidx >= 0 && oidx < NB * RR * OO)
        out[oidx] = b_out[oidx % (RR * OO)];
}

// ---------------------------------------------------------------------------
// GRU combine
// ---------------------------------------------------------------------------
__global__ void gru_combine_kernel(const float* __restrict__ gi,
                                   const float* __restrict__ gh,
                                   const float* __restrict__ bih,
                                   const float* __restrict__ bhh,
                                   const float* __restrict__ hprev,
                                   float* __restrict__ hout,
                                   const float* __restrict__ extra_in,
                                   float* __restrict__ extra_out,
                                   int mode) {
    gdc_launch();
    gdc_wait();
    int idx = blockIdx.x * 256 + threadIdx.x;
    if (idx >= NB * H2) return;
    int n = idx >> 10;
    int j = idx & (H2 - 1);
    const float* gin = gi + (size_t)n * H3;
    const float* ghn = gh + (size_t)n * H3;
    float ir = gin[j]           + bih[j];
    float iz = gin[j + H2]      + bih[j + H2];
    float in_ = gin[j + 2 * H2] + bih[j + 2 * H2];
    float hr = ghn[j]           + bhh[j];
    float hz = ghn[j + H2]      + bhh[j + H2];
    float hn = ghn[j + 2 * H2]  + bhh[j + 2 * H2];
    float r = fast_sigmoid(ir + hr);
    float z = fast_sigmoid(iz + hz);
    float nn = fast_tanh(in_ + r * hn);
    float h = (1.0f - z) * nn + z * hprev[idx];
    hout[idx] = h;
    if (mode == 1) {
        extra_out[(size_t)n * H4 + H2 + j] = h;
    } else if (mode == 2) {
        extra_out[idx] = extra_in[idx] + h;
    }
}

// ---------------------------------------------------------------------------
// Fused attention. PDL: Wattn smem load pre-wait, dp load post-wait.
// ---------------------------------------------------------------------------
__global__ void __launch_bounds__(256) attn_fused_kernel(
    const float* __restrict__ attW, const float* __restrict__ enc,
    const float* __restrict__ dp, const float* __restrict__ Wattn,
    const float* __restrict__ battn, const int* __restrict__ lengths,
    float* __restrict__ dec_in, float* __restrict__ ssum) {
    __shared__ float dps[H2];
    __shared__ float was[H2];
    __shared__ float ss[CH];
    int n = blockIdx.y;
    int t0 = blockIdx.x * CH;
    int len = lengths[n];
    if (t0 >= len) return;
    int kmax = min(CH, len - t0);
    int tid = threadIdx.x;

    for (int i = tid; i < H2; i += 256) was[i] = Wattn[i];
    if (tid < CH) ss[tid] = 0.0f;
    gdc_launch();
    gdc_wait();
    for (int i = tid; i < H2; i += 256) dps[i] = dp[(size_t)n * H2 + i];
    __syncthreads();

    int warp = tid >> 5, lane = tid & 31;
    float bb = battn[0];
#pragma unroll
    for (int rep = 0; rep < CH / 8; rep++) {
        int lt = warp + rep * 8;
        if (lt < kmax) {
            const float4* row = (const float4*)(attW + ((size_t)n * TT + t0 + lt) * H2);
            const float4* d4p = (const float4*)dps;
            const float4* w4p = (const float4*)was;
            float s = 0.0f;
#pragma unroll
            for (int it = 0; it < 8; it++) {
                int i = it * 32 + lane;
                float4 v = row[i];
                float4 dd = d4p[i];
                float4 ww = w4p[i];
                s += approx_tanh(v.x + dd.x) * ww.x
                   + approx_tanh(v.y + dd.y) * ww.y
                   + approx_tanh(v.z + dd.z) * ww.z
                   + approx_tanh(v.w + dd.w) * ww.w;
            }
#pragma unroll
            for (int o = 16; o; o >>= 1) s += __shfl_xor_sync(0xffffffffu, s, o);
            if (lane == 0) ss[lt] = __expf(s + bb);
        }
    }
    __syncthreads();

    if (warp == 0) {
        float v = (lane < CH) ? ss[lane] : 0.0f;
#pragma unroll
        for (int o = 16; o; o >>= 1) v += __shfl_xor_sync(0xffffffffu, v, o);
        if (lane == 0) atomicAdd(&ssum[n], v);
    }

    int h = tid * 4;
    const float* ebase = enc + (size_t)n * TT * H2 + (size_t)t0 * H2 + h;
    float ax = 0.f, ay = 0.f, az = 0.f, aw = 0.f;
#pragma unroll 4
    for (int t = 0; t < kmax; t++) {
        float w = ss[t];
        float4 e = *(const float4*)(ebase + (size_t)t * H2);
        ax += w * e.x; ay += w * e.y; az += w * e.z; aw += w * e.w;
    }
    red4(&dec_in[(size_t)n * H4 + h], ax, ay, az, aw);
}

// ---------------------------------------------------------------------------
// L2 prefetch of late-stage weights (one float per 128B line) — now covers
// stage-8 weights (Wih_d1, W_sc) plus stage-10/12 (Wih_d2, W_out).
// ---------------------------------------------------------------------------
__global__ void prefetch_kernel(const float4* __restrict__ a, int n4a,
                                const float4* __restrict__ b, int n4b,
                                const float4* __restrict__ c, int n4c,
                                const float4* __restrict__ e, int n4e) {
    float s = 0.0f;
    int stride = gridDim.x * blockDim.x * 8;
    int base = (blockIdx.x * blockDim.x + threadIdx.x) * 8;
    for (int i = base; i < n4a; i += stride) s += a[i].x;
    for (int i = base; i < n4b; i += stride) s += b[i].x;
    for (int i = base; i < n4c; i += stride) s += c[i].x;
    for (int i = base; i < n4e; i += stride) s += e[i].x;
    if (s == 1.2345e38f) g_scratch[OFF_DUMMY] = s;   // never fires; defeats DCE
}

// ---------------------------------------------------------------------------
// Host helpers
// ---------------------------------------------------------------------------
static bool s_pdl = true;   // flips off once if ex-launch unsupported

template <typename F, typename... Args>
static inline void launch_pdl(F kern, dim3 g, dim3 b, Args... args) {
    if (s_pdl) {
        cudaLaunchConfig_t cfg = {};
        cfg.gridDim = g; cfg.blockDim = b; cfg.stream = 0;
        cudaLaunchAttribute at[1];
        at[0].id = cudaLaunchAttributeProgrammaticStreamSerialization;
        at[0].val.programmaticStreamSerializationAllowed = 1;
        cfg.attrs = at; cfg.numAttrs = 1;
        if (cudaLaunchKernelEx(&cfg, kern, args...) == cudaSuccess) return;
        s_pdl = false;
    }
    kern<<<g, b>>>(args...);
}

static inline int pack_batch(GemmBatch& P, GD* ds, int n) {
    int start = 0;
    for (int i = 0; i < n; i++) {
        ds[i].start = start;
        start += ds[i].nBlocks;
        P.d[i] = ds[i];
    }
    for (int i = n; i < 4; i++) P.d[i] = P.d[n - 1];
    P.n = n;
    return start;
}

static inline void launch_gemms_pdl(GD* ds, int n) {
    GemmBatch P;
    int total = pack_batch(P, ds, n);
    launch_pdl(multi_gemm_kernel, dim3(total), dim3(128), P);
}

static inline void launch_gemms_side(GD* ds, int n, cudaStream_t st) {
    GemmBatch P;
    int total = pack_batch(P, ds, n);
    multi_gemm_kernel<<<total, 128, 0, st>>>(P);
}

extern "C" void kernel_launch(void* const* d_in, const int* in_sizes, int n_in,
                              void* d_out, int out_size) {
    static bool s_init = false;
    static cudaStream_t s_side = 0;
    static cudaEvent_t s_ev0 = 0, s_evgh = 0, s_ev1 = 0, s_ev2 = 0;
    static bool s_ok = false;
    if (!s_init) {
        s_init = true;
        cudaStream_t st;
        cudaEvent_t e0, eg, e1, e2;
        if (cudaStreamCreateWithFlags(&st, cudaStreamNonBlocking) == cudaSuccess &&
            cudaEventCreateWithFlags(&e0, cudaEventDisableTiming) == cudaSuccess &&
            cudaEventCreateWithFlags(&eg, cudaEventDisableTiming) == cudaSuccess &&
            cudaEventCreateWithFlags(&e1, cudaEventDisableTiming) == cudaSuccess &&
            cudaEventCreateWithFlags(&e2, cudaEventDisableTiming) == cudaSuccess) {
            s_side = st; s_ev0 = e0; s_evgh = eg; s_ev1 = e1; s_ev2 = e2;
            s_ok = true;
        }
    }

    const float* input_enc   = (const float*)d_in[0];
    const float* attW_enc    = (const float*)d_in[1];
    const float* input_dec   = (const float*)d_in[2];
    const int*   lengths     = (const int*)  d_in[3];
    const float* hidden_att  = (const float*)d_in[4];
    const float* hidden_dec1 = (const float*)d_in[5];
    const float* hidden_dec2 = (const float*)d_in[6];
    const float* W_pre1 = (const float*)d_in[7];
    const float* b_pre1 = (const float*)d_in[8];
    const float* W_pre2 = (const float*)d_in[9];
    const float* b_pre2 = (const float*)d_in[10];
    const float* Wih_att = (const float*)d_in[11];
    const float* Whh_att = (const float*)d_in[12];
    const float* bih_att = (const float*)d_in[13];
    const float* bhh_att = (const float*)d_in[14];
    const float* W_ld  = (const float*)d_in[15];
    const float* b_ld  = (const float*)d_in[16];
    const float* W_attn = (const float*)d_in[17];
    const float* b_attn = (const float*)d_in[18];
    const float* W_sc  = (const float*)d_in[19];
    const float* b_sc  = (const float*)d_in[20];
    const float* Wih_d1 = (const float*)d_in[21];
    const float* Whh_d1 = (const float*)d_in[22];
    const float* bih_d1 = (const float*)d_in[23];
    const float* bhh_d1 = (const float*)d_in[24];
    const float* Wih_d2 = (const float*)d_in[25];
    const float* Whh_d2 = (const float*)d_in[26];
    const float* bih_d2 = (const float*)d_in[27];
    const float* bhh_d2 = (const float*)d_in[28];
    const float* W_out = (const float*)d_in[29];
    const float* b_out = (const float*)d_in[30];

    float* out = (float*)d_out;

    float* sc = nullptr;
    cudaGetSymbolAddress((void**)&sc, g_scratch);

    float* gi_att = sc + OFF_GI_ATT;
    float* gh_att = sc + OFF_GH_ATT;
    float* gi_d1  = sc + OFF_GI_D1;
    float* gh_d1  = sc + OFF_GH_D1;
    float* gi_d2  = sc + OFF_GI_D2;
    float* gh_d2  = sc + OFF_GH_D2;
    float* pre_a  = sc + OFF_PRE_A;
    float* pre    = sc + OFF_PRE;
    float* dp     = sc + OFF_DP;
    float* resid_sc = sc + OFF_RESID_SC;
    float* resid  = sc + OFF_RESID;
    float* resid2 = sc + OFF_RESID2;
    float* dec_in = sc + OFF_DECIN;
    float* ssum   = sc + OFF_SSUM;
    const int* flags = (const int*)(sc + OFF_FLAGS);

    bool full_out = (out_size >= NB * RR * OO + 3 * NB * H2);
    float* h_att_out = full_out ? out + NB * RR * OO : sc + OFF_HATT;
    float* h_d1_out  = full_out ? h_att_out + NB * H2 : sc + OFF_HD1;
    float* h_d2_out  = full_out ? h_d1_out + NB * H2 : sc + OFF_HD2;

    cudaStream_t side = s_ok ? s_side : (cudaStream_t)0;

    // 1) init: flags + zeroing + bias broadcasts (out biases post-wait)
    launch_pdl(init_kernel, dim3((INIT_TOTAL + 255) / 256), dim3(256),
               out, b_pre1, b_pre2, b_ld, b_sc, b_out,
               hidden_att, hidden_dec1, hidden_dec2);

    // fork 1: gh GEMMs on side stream (mostly flag-skipped; off critical path)
    if (s_ok) {
        cudaEventRecord(s_ev0, 0);
        cudaStreamWaitEvent(side, s_ev0, 0);
    }
    {
        GD ds[3] = {
            mk(hidden_att,  H2, 0, Whh_att, H2, gh_att, H3, H2, 256, 32, 0, flags + 0),
            mk(hidden_dec1, H2, 0, Whh_d1,  H2, gh_d1,  H3, H2, 256, 32, 0, flags + 16),
            mk(hidden_dec2, H2, 0, Whh_d2,  H2, gh_d2,  H3, H2, 256, 32, 0, flags + 32),
        };
        launch_gemms_side(ds, 3, side);
    }
    if (s_ok) cudaEventRecord(s_evgh, side);

    // 2) pre_a = input_dec @ W_pre1^T + b1   (80 blocks)
    {
        GD ds[1] = { mk(input_dec, OO, 0, W_pre1, OO, pre_a, H2, OO, 16, 16, 0, 0) };
        launch_gemms_pdl(ds, 1);
    }
    // 3) pre = relu(pre_a) @ W_pre2^T + b2   (512 blocks)
    {
        GD ds[1] = { mk(pre_a, H2, 1, W_pre2, H2, pre, HH, H2, 16, 16, 0, 0) };
        launch_gemms_pdl(ds, 1);
    }
    // 4) gi_att = relu(pre) @ Wih_att^T   (768 blocks)
    {
        GD ds[1] = { mk(pre, HH, 1, Wih_att, HH, gi_att, H3, HH, 32, 32, 0, 0) };
        launch_gemms_pdl(ds, 1);
    }
    // join gh before combine
    if (s_ok) cudaStreamWaitEvent(0, s_evgh, 0);
    // 5) h_att (also writes dec_in h-half)
    launch_pdl(gru_combine_kernel, dim3((NB * H2 + 255) / 256), dim3(256),
               (const float*)gi_att, (const float*)gh_att, bih_att, bhh_att,
               hidden_att, h_att_out, (const float*)0, dec_in, 1);

    // fork 2: side stream computes h_att-half GEMMs + prefetch under attention
    if (s_ok) {
        cudaEventRecord(s_ev1, 0);
        cudaStreamWaitEvent(side, s_ev1, 0);
    }
    {
        GD ds[2] = {
            mk(h_att_out, H2, 0, Wih_d1 + H2, H4, gi_d1,    H3, H2, 128, 32, 0, 0),
            mk(h_att_out, H2, 0, W_sc   + H2, H4, resid_sc, H2, H2, 128, 32, 0, 0),
        };
        launch_gemms_side(ds, 2, side);   // 512 blocks on side stream
    }
    prefetch_kernel<<<128, 256, 0, side>>>(
        (const float4*)Wih_d2, (H3 * H2) / 4,
        (const float4*)W_out, (RR * OO * H2) / 4,
        (const float4*)Wih_d1, (H3 * H4) / 4,
        (const float4*)W_sc, (H2 * H4) / 4);
    if (s_ok) cudaEventRecord(s_ev2, side);

    // 6) dec_proj   (512 blocks)
    {
        GD ds[1] = { mk(h_att_out, H2, 0, W_ld, H2, dp, H2, H2, 32, 32, 0, 0) };
        launch_gemms_pdl(ds, 1);
    }
    // 7) fused attention (1600 blocks) — side-stream GEMMs overlap here
    launch_pdl(attn_fused_kernel, dim3(NCHUNK, NB), dim3(256),
               attW_enc, input_enc, (const float*)dp, W_attn, b_attn,
               lengths, dec_in, ssum);
    // 8) attn-half GEMMs: K=1024, normalize on load (1024 blocks)
    {
        GD ds[2] = {
            mk(dec_in, H4, 2, Wih_d1, H4, gi_d1,    H3, H2, 64, 32, ssum, 0),
            mk(dec_in, H4, 2, W_sc,   H4, resid_sc, H2, H2, 64, 32, ssum, 0),
        };
        launch_gemms_pdl(ds, 2);
    }
    // join side stream before consuming gi_d1 / resid_sc
    if (s_ok) cudaStreamWaitEvent(0, s_ev2, 0);

    // 9) h_dec1 + residual
    launch_pdl(gru_combine_kernel, dim3((NB * H2 + 255) / 256), dim3(256),
               (const float*)gi_d1, (const float*)gh_d1, bih_d1, bhh_d1,
               hidden_dec1, h_d1_out, (const float*)resid_sc, resid, 2);
    // 10) gi_d2   (768 blocks)
    {
        GD ds[1] = { mk(resid, H2, 0, Wih_d2, H2, gi_d2, H3, H2, 64, 32, 0, 0) };
        launch_gemms_pdl(ds, 1);
    }
    // 11) h_dec2 + residual2
    launch_pdl(gru_combine_kernel, dim3((NB * H2 + 255) / 256), dim3(256),
               (const float*)gi_d2, (const float*)gh_d2, bih_d2, bhh_d2,
               hidden_dec2, h_d2_out, (const float*)resid, resid2, 2);
    // 12) output projection   (192 blocks)
    {
        GD ds[1] = { mk(resid2, H2, 0, W_out, H2, out, RR * OO, H2, 16, 16, 0, 0) };
        launch_gemms_pdl(ds, 1);
    }
}